// round 14
// baseline (speedup 1.0000x reference)
#include <cuda_runtime.h>
#include <cuda_bf16.h>
#include <cstdint>

// Output pattern, shape [2, G*N*N] flattened row-major, FLOAT32 values:
//   half 0: out[g*N*N + i]     = float(i / N)   (row index)
//   half 1: out[H + g*N*N + i] = float(i % N)   (col index),  H = G*N*N
// Pure write-only stream (512 MiB for N=4096, G=4); inputs' values unused.
//
// Measured design space (R3-R13):
//  - (R4)  per-instruction warp footprint = contiguous fully-covered 2KB span
//          (thread = one float4/STG); wider contiguous per-thread tiling ->
//          L2/HBM read-modify-write, +83%.
//  - (R8)  persistent grid +9%; (R10) 1024t one-shot stores +22% (ALU-bound).
//  - (R12/R13) 256t x ITERS=4 unrolled: kernel 71.2us @ 84.5% DRAM — ceiling.
//  - R14 probe: 128t x ITERS=8 — deeper back-to-back STG.128 batch per warp
//          (front-batched store MLP 8, prologue amortized over 128B/thread);
//          2x CTAs/SM at regs=28 keeps SM warp count unchanged.

template <int ITERS>
__global__ void fa_row_split_kernel_t(float* __restrict__ out,
                                      unsigned N, unsigned G,
                                      long long halfElems) {
    const unsigned r = blockIdx.y;                 // row index
    const unsigned z = blockIdx.z;
    const bool colHalf = (z >= G);
    const unsigned g = colHalf ? (z - G) : z;
    const long long NNll = (long long)N * (long long)N;

    const long long base = (colHalf ? halfElems : 0LL)
                         + (long long)g * NNll
                         + (long long)r * (long long)N
                         + (long long)(threadIdx.x * 4u);

    const unsigned stride = blockDim.x * 4u;       // floats per block-sweep

    if (colHalf) {
        const float c0 = (float)(threadIdx.x * 4u);
#pragma unroll
        for (int j = 0; j < ITERS; j++) {
            float c = c0 + (float)(j) * (float)stride;
            __stcs(reinterpret_cast<float4*>(out + base + (long long)j * stride),
                   make_float4(c, c + 1.0f, c + 2.0f, c + 3.0f));
        }
    } else {
        const float rf = (float)r;
        const float4 rv = make_float4(rf, rf, rf, rf);
#pragma unroll
        for (int j = 0; j < ITERS; j++) {
            __stcs(reinterpret_cast<float4*>(out + base + (long long)j * stride),
                   rv);
        }
    }
}

// Runtime-iters variant for other N multiples of 1024 (R9/R11 shape).
__global__ void fa_row_split_kernel(float* __restrict__ out,
                                    unsigned N, unsigned G,
                                    long long halfElems) {
    const unsigned r = blockIdx.y;
    const unsigned z = blockIdx.z;
    const bool colHalf = (z >= G);
    const unsigned g = colHalf ? (z - G) : z;
    const long long NNll = (long long)N * (long long)N;

    long long base = (colHalf ? halfElems : 0LL)
                   + (long long)g * NNll
                   + (long long)r * (long long)N
                   + (long long)(threadIdx.x * 4u);

    const unsigned stride = blockDim.x * 4u;
    const unsigned iters = N / stride;

    if (colHalf) {
        float c = (float)(threadIdx.x * 4u);
        for (unsigned j = 0; j < iters; j++) {
            __stcs(reinterpret_cast<float4*>(out + base),
                   make_float4(c, c + 1.0f, c + 2.0f, c + 3.0f));
            base += stride;
            c += (float)stride;
        }
    } else {
        const float rf = (float)r;
        const float4 rv = make_float4(rf, rf, rf, rf);
        for (unsigned j = 0; j < iters; j++) {
            __stcs(reinterpret_cast<float4*>(out + base), rv);
            base += stride;
        }
    }
}

// Generic path: thread = one float4 per half, N % 4 == 0.
__global__ void fa_vec_kernel(float* __restrict__ out,
                              unsigned N, unsigned NN, long long halfElems) {
    unsigned i4 = ((unsigned)blockIdx.x * blockDim.x + threadIdx.x) * 4u;
    if (i4 >= NN) return;
    unsigned r = i4 / N;
    unsigned c = i4 - r * N;
    long long base = (long long)blockIdx.y * (long long)NN + (long long)i4;
    float rf = (float)r, cf = (float)c;
    __stcs(reinterpret_cast<float4*>(out + base),
           make_float4(rf, rf, rf, rf));
    __stcs(reinterpret_cast<float4*>(out + halfElems + base),
           make_float4(cf, cf + 1.0f, cf + 2.0f, cf + 3.0f));
}

// Scalar fallback.
__global__ void fa_scalar_kernel(float* __restrict__ out,
                                 unsigned N, unsigned NN, long long halfElems) {
    unsigned i = (unsigned)blockIdx.x * blockDim.x + threadIdx.x;
    if (i >= NN) return;
    unsigned r = i / N;
    unsigned c = i - r * N;
    long long base = (long long)blockIdx.y * (long long)NN + (long long)i;
    out[base] = (float)r;
    out[halfElems + base] = (float)c;
}

extern "C" void kernel_launch(void* const* d_in, const int* in_sizes, int n_in,
                              void* d_out, int out_size) {
    (void)d_in;
    // Derive N: the input size s with out_size == 2*G*s*s, integer 1<=G<=4096.
    long long N = 0, G = 0;
    for (int i = 0; i < n_in; i++) {
        long long s = (long long)in_sizes[i];
        if (s <= 0) continue;
        long long denom = 2LL * s * s;
        if (denom <= 0) continue;
        if ((long long)out_size % denom != 0) continue;
        long long g = (long long)out_size / denom;
        if (g >= 1 && g <= 4096) { N = s; G = g; break; }
    }
    if (N == 0) {
        N = (long long)in_sizes[2];
        long long denom = 2LL * N * N;
        G = (denom > 0 && (long long)out_size % denom == 0)
                ? (long long)out_size / denom : 1;
    }

    const long long NNll = N * N;
    const unsigned NN = (unsigned)NNll;
    const long long halfElems = G * NNll;
    float* out = (float*)d_out;

    if (N == 4096 && 2 * G <= 65535LL) {
        // R14 probe: 128 threads x ITERS=8 -> 8 back-to-back STG.128/thread.
        dim3 grid(1, (unsigned)N, (unsigned)(2 * G));
        fa_row_split_kernel_t<8><<<grid, 128>>>(out, (unsigned)N,
                                                (unsigned)G, halfElems);
    } else if ((N % 1024) == 0 && N <= 65535LL && 2 * G <= 65535LL) {
        dim3 grid(1, (unsigned)N, (unsigned)(2 * G));
        fa_row_split_kernel<<<grid, 256>>>(out, (unsigned)N, (unsigned)G,
                                           halfElems);
    } else if ((N % 4) == 0 && NNll <= 0xFFFFFFFFLL) {
        const int threads = 256;
        const unsigned elems4 = NN / 4u;
        unsigned gx = (elems4 + threads - 1) / threads;
        if (gx == 0) gx = 1;
        dim3 grid(gx, (unsigned)G, 1);
        fa_vec_kernel<<<grid, threads>>>(out, (unsigned)N, NN, halfElems);
    } else {
        const int threads = 256;
        unsigned gx = (unsigned)((NNll + threads - 1) / threads);
        if (gx == 0) gx = 1;
        dim3 grid(gx, (unsigned)G, 1);
        fa_scalar_kernel<<<grid, threads>>>(out, (unsigned)N, NN, halfElems);
    }
}

// round 15
// speedup vs baseline: 1.0065x; 1.0065x over previous
#include <cuda_runtime.h>
#include <cuda_bf16.h>
#include <cstdint>

// Output pattern, shape [2, G*N*N] flattened row-major, FLOAT32 values:
//   half 0: out[g*N*N + i]     = float(i / N)   (row index)
//   half 1: out[H + g*N*N + i] = float(i % N)   (col index),  H = G*N*N
// Pure write-only stream (512 MiB for N=4096, G=4); inputs' values unused.
//
// FINAL — converged optimum, full design-space sweep R3-R14:
//  - (R4)  per-instruction warp footprint = contiguous fully-covered 2KB span
//          (thread = one float4/STG); wider contiguous per-thread tiling ->
//          L2/HBM read-modify-write, +83% time.
//  - (R8)  persistent grid +9% (serialized units lower store pressure).
//  - Store-batch depth sweep: 16B/thread (1024t, R10) +22% ALU-bound;
//          64B/thread (256t x ITERS=4, R12/R13) BEST 71.2us @ 84.5% DRAM;
//          128B/thread (128t x ITERS=8, R14) +2.5% (fewer concurrent warps
//          feeding the LSU despite deeper per-warp batches).
//  - Ceiling: ~7.5 TB/s pure write stream; the 2KB-grain L2 address hash
//          neutralizes locality engineering beyond the warp span.
//  - __stcs (evict-first): output is 4x L2 capacity and never re-read.
//
// Shape: 256-thread blocks, grid (1, N, 2G); z<G row-half, z>=G col-half.
// Each block emits ONE 16KB row as a pure stream: 4 compile-time-unrolled
// back-to-back STG.128 per thread off one base register.

template <int ITERS>
__global__ void fa_row_split_kernel_t(float* __restrict__ out,
                                      unsigned N, unsigned G,
                                      long long halfElems) {
    const unsigned r = blockIdx.y;                 // row index
    const unsigned z = blockIdx.z;
    const bool colHalf = (z >= G);
    const unsigned g = colHalf ? (z - G) : z;
    const long long NNll = (long long)N * (long long)N;

    const long long base = (colHalf ? halfElems : 0LL)
                         + (long long)g * NNll
                         + (long long)r * (long long)N
                         + (long long)(threadIdx.x * 4u);

    const unsigned stride = blockDim.x * 4u;       // 1024 floats (256 thr)

    if (colHalf) {
        const float c0 = (float)(threadIdx.x * 4u);
#pragma unroll
        for (int j = 0; j < ITERS; j++) {
            float c = c0 + (float)j * (float)stride;
            __stcs(reinterpret_cast<float4*>(out + base + (long long)j * stride),
                   make_float4(c, c + 1.0f, c + 2.0f, c + 3.0f));
        }
    } else {
        const float rf = (float)r;
        const float4 rv = make_float4(rf, rf, rf, rf);
#pragma unroll
        for (int j = 0; j < ITERS; j++) {
            __stcs(reinterpret_cast<float4*>(out + base + (long long)j * stride),
                   rv);
        }
    }
}

// Runtime-iters variant for other N multiples of 1024.
__global__ void fa_row_split_kernel(float* __restrict__ out,
                                    unsigned N, unsigned G,
                                    long long halfElems) {
    const unsigned r = blockIdx.y;
    const unsigned z = blockIdx.z;
    const bool colHalf = (z >= G);
    const unsigned g = colHalf ? (z - G) : z;
    const long long NNll = (long long)N * (long long)N;

    long long base = (colHalf ? halfElems : 0LL)
                   + (long long)g * NNll
                   + (long long)r * (long long)N
                   + (long long)(threadIdx.x * 4u);

    const unsigned stride = blockDim.x * 4u;
    const unsigned iters = N / stride;

    if (colHalf) {
        float c = (float)(threadIdx.x * 4u);
        for (unsigned j = 0; j < iters; j++) {
            __stcs(reinterpret_cast<float4*>(out + base),
                   make_float4(c, c + 1.0f, c + 2.0f, c + 3.0f));
            base += stride;
            c += (float)stride;
        }
    } else {
        const float rf = (float)r;
        const float4 rv = make_float4(rf, rf, rf, rf);
        for (unsigned j = 0; j < iters; j++) {
            __stcs(reinterpret_cast<float4*>(out + base), rv);
            base += stride;
        }
    }
}

// Generic path: thread = one float4 per half, N % 4 == 0.
__global__ void fa_vec_kernel(float* __restrict__ out,
                              unsigned N, unsigned NN, long long halfElems) {
    unsigned i4 = ((unsigned)blockIdx.x * blockDim.x + threadIdx.x) * 4u;
    if (i4 >= NN) return;
    unsigned r = i4 / N;
    unsigned c = i4 - r * N;
    long long base = (long long)blockIdx.y * (long long)NN + (long long)i4;
    float rf = (float)r, cf = (float)c;
    __stcs(reinterpret_cast<float4*>(out + base),
           make_float4(rf, rf, rf, rf));
    __stcs(reinterpret_cast<float4*>(out + halfElems + base),
           make_float4(cf, cf + 1.0f, cf + 2.0f, cf + 3.0f));
}

// Scalar fallback.
__global__ void fa_scalar_kernel(float* __restrict__ out,
                                 unsigned N, unsigned NN, long long halfElems) {
    unsigned i = (unsigned)blockIdx.x * blockDim.x + threadIdx.x;
    if (i >= NN) return;
    unsigned r = i / N;
    unsigned c = i - r * N;
    long long base = (long long)blockIdx.y * (long long)NN + (long long)i;
    out[base] = (float)r;
    out[halfElems + base] = (float)c;
}

extern "C" void kernel_launch(void* const* d_in, const int* in_sizes, int n_in,
                              void* d_out, int out_size) {
    (void)d_in;
    // Derive N: the input size s with out_size == 2*G*s*s, integer 1<=G<=4096.
    long long N = 0, G = 0;
    for (int i = 0; i < n_in; i++) {
        long long s = (long long)in_sizes[i];
        if (s <= 0) continue;
        long long denom = 2LL * s * s;
        if (denom <= 0) continue;
        if ((long long)out_size % denom != 0) continue;
        long long g = (long long)out_size / denom;
        if (g >= 1 && g <= 4096) { N = s; G = g; break; }
    }
    if (N == 0) {
        N = (long long)in_sizes[2];
        long long denom = 2LL * N * N;
        G = (denom > 0 && (long long)out_size % denom == 0)
                ? (long long)out_size / denom : 1;
    }

    const long long NNll = N * N;
    const unsigned NN = (unsigned)NNll;
    const long long halfElems = G * NNll;
    float* out = (float*)d_out;
    const int threads = 256;

    if (N == 4096 && 2 * G <= 65535LL) {
        // Measured optimum: 256 threads x ITERS=4 (64B/thread store batch).
        dim3 grid(1, (unsigned)N, (unsigned)(2 * G));
        fa_row_split_kernel_t<4><<<grid, threads>>>(out, (unsigned)N,
                                                    (unsigned)G, halfElems);
    } else if ((N % (threads * 4)) == 0 && N <= 65535LL && 2 * G <= 65535LL) {
        dim3 grid(1, (unsigned)N, (unsigned)(2 * G));
        fa_row_split_kernel<<<grid, threads>>>(out, (unsigned)N, (unsigned)G,
                                               halfElems);
    } else if ((N % 4) == 0 && NNll <= 0xFFFFFFFFLL) {
        const unsigned elems4 = NN / 4u;
        unsigned gx = (elems4 + threads - 1) / threads;
        if (gx == 0) gx = 1;
        dim3 grid(gx, (unsigned)G, 1);
        fa_vec_kernel<<<grid, threads>>>(out, (unsigned)N, NN, halfElems);
    } else {
        unsigned gx = (unsigned)((NNll + threads - 1) / threads);
        if (gx == 0) gx = 1;
        dim3 grid(gx, (unsigned)G, 1);
        fa_scalar_kernel<<<grid, threads>>>(out, (unsigned)N, NN, halfElems);
    }
}

// round 16
// speedup vs baseline: 1.0078x; 1.0013x over previous
#include <cuda_runtime.h>
#include <cuda_bf16.h>
#include <cstdint>

// Output pattern, shape [2, G*N*N] flattened row-major, FLOAT32 values:
//   half 0: out[g*N*N + i]     = float(i / N)   (row index)
//   half 1: out[H + g*N*N + i] = float(i % N)   (col index),  H = G*N*N
// Pure write-only stream (512 MiB for N=4096, G=4); inputs' values unused.
//
// Design space measured R3-R15:
//  - (R4)  per-instruction warp footprint = contiguous fully-covered 2KB span
//          (thread = one float4/STG); violating -> L2/HBM RMW, +83%.
//  - (R8)  persistent grid +9%.
//  - Store-batch depth: 16B/thread (1024t, no loop) +22%; 64B/thread
//          (256t x ITERS=4) best 71.2us @ 84.5% DRAM; 128B/thread
//          (128t x ITERS=8) +2.5%.
//  - R16 probe: 32B/thread (512t x ITERS=2) — the last untested interior
//          point; more concurrent store-issuing warps per CTA, prologue
//          still amortized over 2 unrolled STG.128.
//  - Ceiling: ~7.5 TB/s pure write stream; 2KB-grain L2 hash neutralizes
//          locality beyond the warp span. __stcs: never-re-read output.

template <int ITERS>
__global__ void fa_row_split_kernel_t(float* __restrict__ out,
                                      unsigned N, unsigned G,
                                      long long halfElems) {
    const unsigned r = blockIdx.y;                 // row index
    const unsigned z = blockIdx.z;
    const bool colHalf = (z >= G);
    const unsigned g = colHalf ? (z - G) : z;
    const long long NNll = (long long)N * (long long)N;

    const long long base = (colHalf ? halfElems : 0LL)
                         + (long long)g * NNll
                         + (long long)r * (long long)N
                         + (long long)(threadIdx.x * 4u);

    const unsigned stride = blockDim.x * 4u;       // floats per block-sweep

    if (colHalf) {
        const float c0 = (float)(threadIdx.x * 4u);
#pragma unroll
        for (int j = 0; j < ITERS; j++) {
            float c = c0 + (float)j * (float)stride;
            __stcs(reinterpret_cast<float4*>(out + base + (long long)j * stride),
                   make_float4(c, c + 1.0f, c + 2.0f, c + 3.0f));
        }
    } else {
        const float rf = (float)r;
        const float4 rv = make_float4(rf, rf, rf, rf);
#pragma unroll
        for (int j = 0; j < ITERS; j++) {
            __stcs(reinterpret_cast<float4*>(out + base + (long long)j * stride),
                   rv);
        }
    }
}

// Runtime-iters variant for other N multiples of 1024 (R9/R11 shape).
__global__ void fa_row_split_kernel(float* __restrict__ out,
                                    unsigned N, unsigned G,
                                    long long halfElems) {
    const unsigned r = blockIdx.y;
    const unsigned z = blockIdx.z;
    const bool colHalf = (z >= G);
    const unsigned g = colHalf ? (z - G) : z;
    const long long NNll = (long long)N * (long long)N;

    long long base = (colHalf ? halfElems : 0LL)
                   + (long long)g * NNll
                   + (long long)r * (long long)N
                   + (long long)(threadIdx.x * 4u);

    const unsigned stride = blockDim.x * 4u;
    const unsigned iters = N / stride;

    if (colHalf) {
        float c = (float)(threadIdx.x * 4u);
        for (unsigned j = 0; j < iters; j++) {
            __stcs(reinterpret_cast<float4*>(out + base),
                   make_float4(c, c + 1.0f, c + 2.0f, c + 3.0f));
            base += stride;
            c += (float)stride;
        }
    } else {
        const float rf = (float)r;
        const float4 rv = make_float4(rf, rf, rf, rf);
        for (unsigned j = 0; j < iters; j++) {
            __stcs(reinterpret_cast<float4*>(out + base), rv);
            base += stride;
        }
    }
}

// Generic path: thread = one float4 per half, N % 4 == 0.
__global__ void fa_vec_kernel(float* __restrict__ out,
                              unsigned N, unsigned NN, long long halfElems) {
    unsigned i4 = ((unsigned)blockIdx.x * blockDim.x + threadIdx.x) * 4u;
    if (i4 >= NN) return;
    unsigned r = i4 / N;
    unsigned c = i4 - r * N;
    long long base = (long long)blockIdx.y * (long long)NN + (long long)i4;
    float rf = (float)r, cf = (float)c;
    __stcs(reinterpret_cast<float4*>(out + base),
           make_float4(rf, rf, rf, rf));
    __stcs(reinterpret_cast<float4*>(out + halfElems + base),
           make_float4(cf, cf + 1.0f, cf + 2.0f, cf + 3.0f));
}

// Scalar fallback.
__global__ void fa_scalar_kernel(float* __restrict__ out,
                                 unsigned N, unsigned NN, long long halfElems) {
    unsigned i = (unsigned)blockIdx.x * blockDim.x + threadIdx.x;
    if (i >= NN) return;
    unsigned r = i / N;
    unsigned c = i - r * N;
    long long base = (long long)blockIdx.y * (long long)NN + (long long)i;
    out[base] = (float)r;
    out[halfElems + base] = (float)c;
}

extern "C" void kernel_launch(void* const* d_in, const int* in_sizes, int n_in,
                              void* d_out, int out_size) {
    (void)d_in;
    // Derive N: the input size s with out_size == 2*G*s*s, integer 1<=G<=4096.
    long long N = 0, G = 0;
    for (int i = 0; i < n_in; i++) {
        long long s = (long long)in_sizes[i];
        if (s <= 0) continue;
        long long denom = 2LL * s * s;
        if (denom <= 0) continue;
        if ((long long)out_size % denom != 0) continue;
        long long g = (long long)out_size / denom;
        if (g >= 1 && g <= 4096) { N = s; G = g; break; }
    }
    if (N == 0) {
        N = (long long)in_sizes[2];
        long long denom = 2LL * N * N;
        G = (denom > 0 && (long long)out_size % denom == 0)
                ? (long long)out_size / denom : 1;
    }

    const long long NNll = N * N;
    const unsigned NN = (unsigned)NNll;
    const long long halfElems = G * NNll;
    float* out = (float*)d_out;

    if (N == 4096 && 2 * G <= 65535LL) {
        // R16 probe: 512 threads x ITERS=2 (32B/thread store batch).
        dim3 grid(1, (unsigned)N, (unsigned)(2 * G));
        fa_row_split_kernel_t<2><<<grid, 512>>>(out, (unsigned)N,
                                                (unsigned)G, halfElems);
    } else if ((N % 1024) == 0 && N <= 65535LL && 2 * G <= 65535LL) {
        dim3 grid(1, (unsigned)N, (unsigned)(2 * G));
        fa_row_split_kernel<<<grid, 256>>>(out, (unsigned)N, (unsigned)G,
                                           halfElems);
    } else if ((N % 4) == 0 && NNll <= 0xFFFFFFFFLL) {
        const int threads = 256;
        const unsigned elems4 = NN / 4u;
        unsigned gx = (elems4 + threads - 1) / threads;
        if (gx == 0) gx = 1;
        dim3 grid(gx, (unsigned)G, 1);
        fa_vec_kernel<<<grid, threads>>>(out, (unsigned)N, NN, halfElems);
    } else {
        const int threads = 256;
        unsigned gx = (unsigned)((NNll + threads - 1) / threads);
        if (gx == 0) gx = 1;
        dim3 grid(gx, (unsigned)G, 1);
        fa_scalar_kernel<<<grid, threads>>>(out, (unsigned)N, NN, halfElems);
    }
}